// round 1
// baseline (speedup 1.0000x reference)
#include <cuda_runtime.h>

#define Bz 4
#define Cc 256
#define Hh 64
#define Ww 64
#define Nn 4096
#define Rr 32
#define TQ 128
#define TK 128

// Scratch (static device arrays; no allocation in kernel_launch)
__device__ float g_D[3][(size_t)Bz * Cc * Nn];     // depthwise outputs [k][b][c][n]
__device__ float g_Fp[3][(size_t)Bz * Nn * Rr];    // pointwise outputs, transposed [k][b][n][r]
__device__ float g_O[(size_t)Bz * Nn * Rr];        // attention output [b][n][r]

// ---------------------------------------------------------------------------
// K1: fused depthwise 3x3 at dilations 1/3/5, one (b,c) plane per block.
// ---------------------------------------------------------------------------
__global__ void k_depthwise(const float* __restrict__ x,
                            const float* __restrict__ w1, const float* __restrict__ b1,
                            const float* __restrict__ w2, const float* __restrict__ b2,
                            const float* __restrict__ w3, const float* __restrict__ b3) {
    __shared__ float xs[Nn];
    int bc = blockIdx.x;            // b*C + c
    int c = bc & (Cc - 1);
    const float* xp = x + (size_t)bc * Nn;
    for (int i = threadIdx.x; i < Nn; i += blockDim.x) xs[i] = xp[i];

    float wa[9], wb[9], wc[9];
#pragma unroll
    for (int i = 0; i < 9; i++) {
        wa[i] = __ldg(&w1[c * 9 + i]);
        wb[i] = __ldg(&w2[c * 9 + i]);
        wc[i] = __ldg(&w3[c * 9 + i]);
    }
    float biasa = __ldg(&b1[c]), biasb = __ldg(&b2[c]), biasc = __ldg(&b3[c]);
    __syncthreads();

    for (int p = threadIdx.x; p < Nn; p += blockDim.x) {
        int h = p >> 6, w = p & 63;
        float d1 = biasa, d2 = biasb, d3 = biasc;
#pragma unroll
        for (int kh = 0; kh < 3; kh++) {
#pragma unroll
            for (int kw = 0; kw < 3; kw++) {
                int i = kh * 3 + kw;
                {   // dilation 1
                    int hh = h + (kh - 1), ww = w + (kw - 1);
                    float v = ((unsigned)hh < 64u && (unsigned)ww < 64u) ? xs[(hh << 6) + ww] : 0.f;
                    d1 = fmaf(wa[i], v, d1);
                }
                {   // dilation 3
                    int hh = h + (kh - 1) * 3, ww = w + (kw - 1) * 3;
                    float v = ((unsigned)hh < 64u && (unsigned)ww < 64u) ? xs[(hh << 6) + ww] : 0.f;
                    d2 = fmaf(wb[i], v, d2);
                }
                {   // dilation 5
                    int hh = h + (kh - 1) * 5, ww = w + (kw - 1) * 5;
                    float v = ((unsigned)hh < 64u && (unsigned)ww < 64u) ? xs[(hh << 6) + ww] : 0.f;
                    d3 = fmaf(wc[i], v, d3);
                }
            }
        }
        g_D[0][(size_t)bc * Nn + p] = d1;
        g_D[1][(size_t)bc * Nn + p] = d2;
        g_D[2][(size_t)bc * Nn + p] = d3;
    }
}

// ---------------------------------------------------------------------------
// K2: pointwise 1x1 C->R per branch (blockIdx.z = branch), output transposed
// to [b][n][r] for the attention kernel. One thread per spatial position.
// ---------------------------------------------------------------------------
__global__ void k_pointwise(const float* __restrict__ pw1, const float* __restrict__ pb1,
                            const float* __restrict__ pw2, const float* __restrict__ pb2,
                            const float* __restrict__ pw3, const float* __restrict__ pb3) {
    __shared__ float wT[Cc * Rr];   // [c][r], 32 KB
    int k = blockIdx.z;
    const float* pw = (k == 0) ? pw1 : ((k == 1) ? pw2 : pw3);
    const float* pb = (k == 0) ? pb1 : ((k == 1) ? pb2 : pb3);

    for (int i = threadIdx.x; i < Cc * Rr; i += blockDim.x) {
        int r = i / Cc, c = i % Cc;
        wT[c * Rr + r] = pw[i];     // pw layout [R][C]
    }
    __syncthreads();

    int b = blockIdx.y;
    int n = blockIdx.x * blockDim.x + threadIdx.x;
    const float* Dk = g_D[k] + (size_t)b * Cc * Nn + n;

    float acc[Rr];
#pragma unroll
    for (int r = 0; r < Rr; r++) acc[r] = __ldg(&pb[r]);

#pragma unroll 4
    for (int c = 0; c < Cc; c++) {
        float v = Dk[(size_t)c * Nn];
        const float4* w4 = (const float4*)(wT + c * Rr);
#pragma unroll
        for (int q = 0; q < 8; q++) {
            float4 ww = w4[q];
            acc[q * 4 + 0] = fmaf(ww.x, v, acc[q * 4 + 0]);
            acc[q * 4 + 1] = fmaf(ww.y, v, acc[q * 4 + 1]);
            acc[q * 4 + 2] = fmaf(ww.z, v, acc[q * 4 + 2]);
            acc[q * 4 + 3] = fmaf(ww.w, v, acc[q * 4 + 3]);
        }
    }
    float4* out = (float4*)(g_Fp[k] + ((size_t)b * Nn + n) * Rr);
#pragma unroll
    for (int q = 0; q < 8; q++)
        out[q] = make_float4(acc[q * 4], acc[q * 4 + 1], acc[q * 4 + 2], acc[q * 4 + 3]);
}

// ---------------------------------------------------------------------------
// K3: fused attention. Q = Fp2, K = Fp3, V = Fp1, d = 32, N = 4096.
// Flash-style: never materialize the NxN matrix. Softmax without max-shift
// (scores are mathematically bounded far below fp32 exp overflow).
// One thread per query row; K/V tiles staged through SMEM (broadcast reads).
// ---------------------------------------------------------------------------
__global__ void k_attn() {
    __shared__ float4 Ks[TK * 8];
    __shared__ float4 Vs[TK * 8];
    int b = blockIdx.y;
    int i = blockIdx.x * TQ + threadIdx.x;

    const float4* Q4 = (const float4*)(g_Fp[1] + ((size_t)b * Nn + i) * Rr);
    float q[Rr];
#pragma unroll
    for (int t = 0; t < 8; t++) {
        float4 v = Q4[t];
        q[4 * t] = v.x; q[4 * t + 1] = v.y; q[4 * t + 2] = v.z; q[4 * t + 3] = v.w;
    }
    float o[Rr];
#pragma unroll
    for (int r = 0; r < Rr; r++) o[r] = 0.f;
    float l = 0.f;

    const float4* Kg = (const float4*)(g_Fp[2] + (size_t)b * Nn * Rr);
    const float4* Vg = (const float4*)(g_Fp[0] + (size_t)b * Nn * Rr);

    for (int j0 = 0; j0 < Nn; j0 += TK) {
        __syncthreads();
#pragma unroll
        for (int t = 0; t < 8; t++) {
            int idx = threadIdx.x + t * TQ;     // 0..1023
            Ks[idx] = Kg[j0 * 8 + idx];
            Vs[idx] = Vg[j0 * 8 + idx];
        }
        __syncthreads();

#pragma unroll 2
        for (int j = 0; j < TK; j++) {
            float s0 = 0.f, s1 = 0.f, s2 = 0.f, s3 = 0.f;
#pragma unroll
            for (int t = 0; t < 8; t++) {
                float4 kk = Ks[j * 8 + t];
                s0 = fmaf(q[4 * t + 0], kk.x, s0);
                s1 = fmaf(q[4 * t + 1], kk.y, s1);
                s2 = fmaf(q[4 * t + 2], kk.z, s2);
                s3 = fmaf(q[4 * t + 3], kk.w, s3);
            }
            float e = __expf((s0 + s1) + (s2 + s3));
            l += e;
#pragma unroll
            for (int t = 0; t < 8; t++) {
                float4 vv = Vs[j * 8 + t];
                o[4 * t + 0] = fmaf(e, vv.x, o[4 * t + 0]);
                o[4 * t + 1] = fmaf(e, vv.y, o[4 * t + 1]);
                o[4 * t + 2] = fmaf(e, vv.z, o[4 * t + 2]);
                o[4 * t + 3] = fmaf(e, vv.w, o[4 * t + 3]);
            }
        }
    }
    float inv = 1.0f / l;
    float4* O4 = (float4*)(g_O + ((size_t)b * Nn + i) * Rr);
#pragma unroll
    for (int t = 0; t < 8; t++)
        O4[t] = make_float4(o[4 * t] * inv, o[4 * t + 1] * inv,
                            o[4 * t + 2] * inv, o[4 * t + 3] * inv);
}

// ---------------------------------------------------------------------------
// K4: conv_out 1x1 (R->C) + bias + residual.
// ---------------------------------------------------------------------------
__global__ void k_out(const float* __restrict__ x, const float* __restrict__ cow,
                      const float* __restrict__ cob, float* __restrict__ out) {
    __shared__ float ws[Cc * Rr];   // [co][r], 32 KB
    for (int i = threadIdx.x; i < Cc * Rr; i += blockDim.x) ws[i] = cow[i];
    __syncthreads();

    int b = blockIdx.y;
    int n = blockIdx.x * blockDim.x + threadIdx.x;

    const float4* O4 = (const float4*)(g_O + ((size_t)b * Nn + n) * Rr);
    float o[Rr];
#pragma unroll
    for (int t = 0; t < 8; t++) {
        float4 v = O4[t];
        o[4 * t] = v.x; o[4 * t + 1] = v.y; o[4 * t + 2] = v.z; o[4 * t + 3] = v.w;
    }

    size_t base = (size_t)b * Cc * Nn + n;
#pragma unroll 2
    for (int co = 0; co < Cc; co++) {
        const float4* w4 = (const float4*)(ws + co * Rr);
        float s0 = 0.f, s1 = 0.f, s2 = 0.f, s3 = 0.f;
#pragma unroll
        for (int t = 0; t < 8; t++) {
            float4 ww = w4[t];
            s0 = fmaf(ww.x, o[4 * t + 0], s0);
            s1 = fmaf(ww.y, o[4 * t + 1], s1);
            s2 = fmaf(ww.z, o[4 * t + 2], s2);
            s3 = fmaf(ww.w, o[4 * t + 3], s3);
        }
        out[base + (size_t)co * Nn] = x[base + (size_t)co * Nn] + ((s0 + s1) + (s2 + s3)) + __ldg(&cob[co]);
    }
}

// ---------------------------------------------------------------------------
extern "C" void kernel_launch(void* const* d_in, const int* in_sizes, int n_in,
                              void* d_out, int out_size) {
    const float* x = (const float*)d_in[0];
    // d_in: 0:x 1:c1_dw_w 2:c1_dw_b 3:c1_pw_w 4:c1_pw_b
    //       5:c2_dw_w 6:c2_dw_b 7:c2_pw_w 8:c2_pw_b
    //       9:c3_dw_w 10:c3_dw_b 11:c3_pw_w 12:c3_pw_b 13:co_w 14:co_b
    k_depthwise<<<Bz * Cc, 256>>>(x,
        (const float*)d_in[1], (const float*)d_in[2],
        (const float*)d_in[5], (const float*)d_in[6],
        (const float*)d_in[9], (const float*)d_in[10]);

    dim3 g2(Nn / 128, Bz, 3);
    k_pointwise<<<g2, 128>>>(
        (const float*)d_in[3],  (const float*)d_in[4],
        (const float*)d_in[7],  (const float*)d_in[8],
        (const float*)d_in[11], (const float*)d_in[12]);

    k_attn<<<dim3(Nn / TQ, Bz), TQ>>>();

    k_out<<<dim3(Nn / 128, Bz), 128>>>(x, (const float*)d_in[13],
                                       (const float*)d_in[14], (float*)d_out);
}

// round 2
// speedup vs baseline: 1.7687x; 1.7687x over previous
#include <cuda_runtime.h>

#define Bz 4
#define Cc 256
#define Nn 4096
#define Rr 32
#define TQ 128
#define TK 128
#define SPLIT 8
#define KCHUNK (Nn / SPLIT)   // 512 keys per split

typedef unsigned long long ull;

// Scratch (static device arrays; no allocation anywhere)
__device__ float g_D[3][(size_t)Bz * Cc * Nn];      // depthwise outputs [k][b][c][n]
__device__ float g_Fp[3][(size_t)Bz * Nn * Rr];     // pointwise outputs [k][b][n][r]
__device__ float g_Po[SPLIT][(size_t)Bz * Nn * Rr]; // attention partial numerators
__device__ float g_Pl[SPLIT][(size_t)Bz * Nn];      // attention partial denominators
__device__ float g_O[(size_t)Bz * Nn * Rr];         // combined attention output

// ---- packed f32x2 helpers (SASS FFMA2: 2 MACs per fma-pipe issue) ----------
__device__ __forceinline__ ull fma2(ull a, ull b, ull c) {
    ull d;
    asm("fma.rn.f32x2 %0, %1, %2, %3;" : "=l"(d) : "l"(a), "l"(b), "l"(c));
    return d;
}
__device__ __forceinline__ ull pack2(float x, float y) {
    ull r; asm("mov.b64 %0, {%1, %2};" : "=l"(r) : "f"(x), "f"(y)); return r;
}
__device__ __forceinline__ float2 unpack2(ull v) {
    float2 f; asm("mov.b64 {%0, %1}, %2;" : "=f"(f.x), "=f"(f.y) : "l"(v)); return f;
}

// ---------------------------------------------------------------------------
// K1: fused depthwise 3x3 at dilations 1/3/5, one (b,c) plane per block.
// ---------------------------------------------------------------------------
__global__ void k_depthwise(const float* __restrict__ x,
                            const float* __restrict__ w1, const float* __restrict__ b1,
                            const float* __restrict__ w2, const float* __restrict__ b2,
                            const float* __restrict__ w3, const float* __restrict__ b3) {
    __shared__ float xs[Nn];
    int bc = blockIdx.x;            // b*C + c
    int c = bc & (Cc - 1);
    const float* xp = x + (size_t)bc * Nn;
    for (int i = threadIdx.x; i < Nn; i += blockDim.x) xs[i] = xp[i];

    float wa[9], wb[9], wc[9];
#pragma unroll
    for (int i = 0; i < 9; i++) {
        wa[i] = __ldg(&w1[c * 9 + i]);
        wb[i] = __ldg(&w2[c * 9 + i]);
        wc[i] = __ldg(&w3[c * 9 + i]);
    }
    float biasa = __ldg(&b1[c]), biasb = __ldg(&b2[c]), biasc = __ldg(&b3[c]);
    __syncthreads();

    for (int p = threadIdx.x; p < Nn; p += blockDim.x) {
        int h = p >> 6, w = p & 63;
        float d1 = biasa, d2 = biasb, d3 = biasc;
#pragma unroll
        for (int kh = 0; kh < 3; kh++) {
#pragma unroll
            for (int kw = 0; kw < 3; kw++) {
                int i = kh * 3 + kw;
                {
                    int hh = h + (kh - 1), ww = w + (kw - 1);
                    float v = ((unsigned)hh < 64u && (unsigned)ww < 64u) ? xs[(hh << 6) + ww] : 0.f;
                    d1 = fmaf(wa[i], v, d1);
                }
                {
                    int hh = h + (kh - 1) * 3, ww = w + (kw - 1) * 3;
                    float v = ((unsigned)hh < 64u && (unsigned)ww < 64u) ? xs[(hh << 6) + ww] : 0.f;
                    d2 = fmaf(wb[i], v, d2);
                }
                {
                    int hh = h + (kh - 1) * 5, ww = w + (kw - 1) * 5;
                    float v = ((unsigned)hh < 64u && (unsigned)ww < 64u) ? xs[(hh << 6) + ww] : 0.f;
                    d3 = fmaf(wc[i], v, d3);
                }
            }
        }
        g_D[0][(size_t)bc * Nn + p] = d1;
        g_D[1][(size_t)bc * Nn + p] = d2;
        g_D[2][(size_t)bc * Nn + p] = d3;
    }
}

// ---------------------------------------------------------------------------
// K2: pointwise 1x1 C->R per branch (blockIdx.z), output [b][n][r]. f32x2.
// ---------------------------------------------------------------------------
__global__ void k_pointwise(const float* __restrict__ pw1, const float* __restrict__ pb1,
                            const float* __restrict__ pw2, const float* __restrict__ pb2,
                            const float* __restrict__ pw3, const float* __restrict__ pb3) {
    __shared__ ull wT2[Cc * 16];    // [c][rp] pairs, 32 KB
    int k = blockIdx.z;
    const float* pw = (k == 0) ? pw1 : ((k == 1) ? pw2 : pw3);
    const float* pb = (k == 0) ? pb1 : ((k == 1) ? pb2 : pb3);

    for (int i = threadIdx.x; i < Cc * 16; i += blockDim.x) {
        int c = i >> 4, rp = i & 15;                // pw layout [R][C]
        wT2[i] = pack2(pw[(2 * rp) * Cc + c], pw[(2 * rp + 1) * Cc + c]);
    }
    __syncthreads();

    int b = blockIdx.y;
    int n = blockIdx.x * blockDim.x + threadIdx.x;
    const float* Dk = g_D[k] + (size_t)b * Cc * Nn + n;

    ull acc2[16];
#pragma unroll
    for (int rp = 0; rp < 16; rp++) acc2[rp] = pack2(__ldg(&pb[2 * rp]), __ldg(&pb[2 * rp + 1]));

#pragma unroll 4
    for (int c = 0; c < Cc; c++) {
        float v = Dk[(size_t)c * Nn];
        ull v2 = pack2(v, v);
        const ulonglong2* w4 = (const ulonglong2*)(wT2 + c * 16);
#pragma unroll
        for (int t = 0; t < 8; t++) {
            ulonglong2 ww = w4[t];
            acc2[2 * t + 0] = fma2(v2, ww.x, acc2[2 * t + 0]);
            acc2[2 * t + 1] = fma2(v2, ww.y, acc2[2 * t + 1]);
        }
    }
    ulonglong2* out = (ulonglong2*)(g_Fp[k] + ((size_t)b * Nn + n) * Rr);
#pragma unroll
    for (int t = 0; t < 8; t++) out[t] = make_ulonglong2(acc2[2 * t], acc2[2 * t + 1]);
}

// ---------------------------------------------------------------------------
// K3: flash attention, split-KV. Q=Fp2, K=Fp3, V=Fp1, d=32.
// Unshifted softmax -> partials combine by pure addition. f32x2 math.
// One query per thread; K/V tiles in SMEM (broadcast reads).
// ---------------------------------------------------------------------------
__global__ void __launch_bounds__(TQ) k_attn() {
    __shared__ ulonglong2 Ks[TK * 8];   // 128 keys x 128 B
    __shared__ ulonglong2 Vs[TK * 8];
    int b = blockIdx.y;
    int split = blockIdx.z;
    int i = blockIdx.x * TQ + threadIdx.x;

    const ulonglong2* Qg = (const ulonglong2*)(g_Fp[1] + ((size_t)b * Nn + i) * Rr);
    ull q2[16];
#pragma unroll
    for (int t = 0; t < 8; t++) {
        ulonglong2 v = Qg[t];
        q2[2 * t] = v.x; q2[2 * t + 1] = v.y;
    }
    ull o2[16];
#pragma unroll
    for (int t = 0; t < 16; t++) o2[t] = 0ULL;
    float l = 0.f;

    const ulonglong2* Kg = (const ulonglong2*)(g_Fp[2] + (size_t)b * Nn * Rr);
    const ulonglong2* Vg = (const ulonglong2*)(g_Fp[0] + (size_t)b * Nn * Rr);

    int j_beg = split * KCHUNK;
    for (int j0 = j_beg; j0 < j_beg + KCHUNK; j0 += TK) {
        __syncthreads();
#pragma unroll
        for (int t = 0; t < 8; t++) {
            int idx = threadIdx.x + t * TQ;     // 0..1023
            Ks[idx] = Kg[(size_t)j0 * 8 + idx];
            Vs[idx] = Vg[(size_t)j0 * 8 + idx];
        }
        __syncthreads();

#pragma unroll 2
        for (int j = 0; j < TK; j++) {
            ull sp0 = 0ULL, sp1 = 0ULL;
#pragma unroll
            for (int t = 0; t < 4; t++) {
                ulonglong2 ka = Ks[j * 8 + 2 * t];
                ulonglong2 kb = Ks[j * 8 + 2 * t + 1];
                sp0 = fma2(q2[4 * t + 0], ka.x, sp0);
                sp1 = fma2(q2[4 * t + 1], ka.y, sp1);
                sp0 = fma2(q2[4 * t + 2], kb.x, sp0);
                sp1 = fma2(q2[4 * t + 3], kb.y, sp1);
            }
            float2 sa = unpack2(sp0), sb = unpack2(sp1);
            float e = __expf((sa.x + sa.y) + (sb.x + sb.y));
            l += e;
            ull e2 = pack2(e, e);
#pragma unroll
            for (int t = 0; t < 4; t++) {
                ulonglong2 va = Vs[j * 8 + 2 * t];
                ulonglong2 vb = Vs[j * 8 + 2 * t + 1];
                o2[4 * t + 0] = fma2(e2, va.x, o2[4 * t + 0]);
                o2[4 * t + 1] = fma2(e2, va.y, o2[4 * t + 1]);
                o2[4 * t + 2] = fma2(e2, vb.x, o2[4 * t + 2]);
                o2[4 * t + 3] = fma2(e2, vb.y, o2[4 * t + 3]);
            }
        }
    }
    ulonglong2* Po = (ulonglong2*)(g_Po[split] + ((size_t)b * Nn + i) * Rr);
#pragma unroll
    for (int t = 0; t < 8; t++) Po[t] = make_ulonglong2(o2[2 * t], o2[2 * t + 1]);
    g_Pl[split][(size_t)b * Nn + i] = l;
}

// ---------------------------------------------------------------------------
// K3b: combine split partials -> g_O (normalized).
// One thread per (b,n,float4-chunk).
// ---------------------------------------------------------------------------
__global__ void k_comb() {
    int gid = blockIdx.x * blockDim.x + threadIdx.x;   // 0 .. B*N*8-1
    int chunk = gid & 7;
    int bn = gid >> 3;

    float l = 0.f;
#pragma unroll
    for (int s = 0; s < SPLIT; s++) l += g_Pl[s][bn];
    float inv = 1.0f / l;

    float4 acc = make_float4(0.f, 0.f, 0.f, 0.f);
#pragma unroll
    for (int s = 0; s < SPLIT; s++) {
        float4 v = ((const float4*)g_Po[s])[(size_t)bn * 8 + chunk];
        acc.x += v.x; acc.y += v.y; acc.z += v.z; acc.w += v.w;
    }
    ((float4*)g_O)[(size_t)bn * 8 + chunk] =
        make_float4(acc.x * inv, acc.y * inv, acc.z * inv, acc.w * inv);
}

// ---------------------------------------------------------------------------
// K4: conv_out 1x1 (R->C) + bias + residual. co split across blockIdx.z.
// ---------------------------------------------------------------------------
__global__ void k_out(const float* __restrict__ x, const float* __restrict__ cow,
                      const float* __restrict__ cob, float* __restrict__ out) {
    __shared__ ull ws2[32 * 16];    // 32 co x 32 r as pairs, 4 KB
    int co0 = blockIdx.z * 32;
    for (int i = threadIdx.x; i < 32 * 16; i += blockDim.x) {
        int idx = 2 * i;            // cow layout [C][R]
        ws2[i] = pack2(cow[co0 * Rr + idx], cow[co0 * Rr + idx + 1]);
    }
    __syncthreads();

    int b = blockIdx.y;
    int n = blockIdx.x * blockDim.x + threadIdx.x;

    const ulonglong2* O4 = (const ulonglong2*)(g_O + ((size_t)b * Nn + n) * Rr);
    ull o2[16];
#pragma unroll
    for (int t = 0; t < 8; t++) {
        ulonglong2 v = O4[t];
        o2[2 * t] = v.x; o2[2 * t + 1] = v.y;
    }

    size_t base = (size_t)b * Cc * Nn + n;
#pragma unroll 2
    for (int co = 0; co < 32; co++) {
        const ulonglong2* w4 = (const ulonglong2*)(ws2 + co * 16);
        ull sp0 = 0ULL, sp1 = 0ULL;
#pragma unroll
        for (int t = 0; t < 4; t++) {
            ulonglong2 ww0 = w4[2 * t];
            ulonglong2 ww1 = w4[2 * t + 1];
            sp0 = fma2(ww0.x, o2[4 * t + 0], sp0);
            sp1 = fma2(ww0.y, o2[4 * t + 1], sp1);
            sp0 = fma2(ww1.x, o2[4 * t + 2], sp0);
            sp1 = fma2(ww1.y, o2[4 * t + 3], sp1);
        }
        float2 sa = unpack2(sp0), sb = unpack2(sp1);
        size_t off = base + (size_t)(co0 + co) * Nn;
        out[off] = x[off] + ((sa.x + sa.y) + (sb.x + sb.y)) + __ldg(&cob[co0 + co]);
    }
}

// ---------------------------------------------------------------------------
extern "C" void kernel_launch(void* const* d_in, const int* in_sizes, int n_in,
                              void* d_out, int out_size) {
    const float* x = (const float*)d_in[0];
    k_depthwise<<<Bz * Cc, 256>>>(x,
        (const float*)d_in[1], (const float*)d_in[2],
        (const float*)d_in[5], (const float*)d_in[6],
        (const float*)d_in[9], (const float*)d_in[10]);

    dim3 g2(Nn / 128, Bz, 3);
    k_pointwise<<<g2, 128>>>(
        (const float*)d_in[3],  (const float*)d_in[4],
        (const float*)d_in[7],  (const float*)d_in[8],
        (const float*)d_in[11], (const float*)d_in[12]);

    k_attn<<<dim3(Nn / TQ, Bz, SPLIT), TQ>>>();

    k_comb<<<(Bz * Nn * 8) / 256, 256>>>();

    k_out<<<dim3(Nn / 128, Bz, Cc / 32), 128>>>(x, (const float*)d_in[13],
                                                (const float*)d_in[14], (float*)d_out);
}

// round 3
// speedup vs baseline: 4.6411x; 2.6241x over previous
#include <cuda_runtime.h>
#include <cuda_bf16.h>

#define Bz 4
#define Cc 256
#define Nn 4096
#define Rr 32
#define TK 64
#define SPLIT 4
#define KCHUNK (Nn / SPLIT)   // 1024 keys per split
#define NT (KCHUNK / TK)      // 16 key tiles per split

typedef unsigned long long ull;
typedef unsigned int uint32;

// Scratch (static device arrays; no allocation anywhere)
__device__ float g_D[3][(size_t)Bz * Cc * Nn];                     // depthwise outputs
__device__ __align__(128) __nv_bfloat16 g_Fpb[3][(size_t)Bz * Nn * Rr];  // Q/K/V bf16 [b][n][r]
__device__ float g_Po[SPLIT][(size_t)Bz * Nn * Rr];                // attention partial numerators
__device__ float g_Pl[SPLIT][(size_t)Bz * Nn];                     // attention partial denominators
__device__ float g_O[(size_t)Bz * Nn * Rr];                        // combined attention output

// ---- packed f32x2 helpers ---------------------------------------------------
__device__ __forceinline__ ull fma2(ull a, ull b, ull c) {
    ull d;
    asm("fma.rn.f32x2 %0, %1, %2, %3;" : "=l"(d) : "l"(a), "l"(b), "l"(c));
    return d;
}
__device__ __forceinline__ ull pack2(float x, float y) {
    ull r; asm("mov.b64 %0, {%1, %2};" : "=l"(r) : "f"(x), "f"(y)); return r;
}
__device__ __forceinline__ float2 unpack2(ull v) {
    float2 f; asm("mov.b64 {%0, %1}, %2;" : "=f"(f.x), "=f"(f.y) : "l"(v)); return f;
}
// pack (lo, hi) floats into bf16x2
__device__ __forceinline__ uint32 cvt2(float hi, float lo) {
    uint32 d; asm("cvt.rn.bf16x2.f32 %0, %1, %2;" : "=r"(d) : "f"(hi), "f"(lo)); return d;
}

// ---- tensor-core helpers ----------------------------------------------------
__device__ __forceinline__ void ldsm4(uint32 r[4], uint32 addr) {
    asm volatile("ldmatrix.sync.aligned.m8n8.x4.shared.b16 {%0,%1,%2,%3}, [%4];"
        : "=r"(r[0]), "=r"(r[1]), "=r"(r[2]), "=r"(r[3]) : "r"(addr));
}
__device__ __forceinline__ void ldsm4t(uint32 r[4], uint32 addr) {
    asm volatile("ldmatrix.sync.aligned.m8n8.x4.trans.shared.b16 {%0,%1,%2,%3}, [%4];"
        : "=r"(r[0]), "=r"(r[1]), "=r"(r[2]), "=r"(r[3]) : "r"(addr));
}
__device__ __forceinline__ void mma16816(float c[4], const uint32 a[4], uint32 b0, uint32 b1) {
    asm volatile("mma.sync.aligned.m16n8k16.row.col.f32.bf16.bf16.f32 "
        "{%0,%1,%2,%3}, {%4,%5,%6,%7}, {%8,%9}, {%0,%1,%2,%3};"
        : "+f"(c[0]), "+f"(c[1]), "+f"(c[2]), "+f"(c[3])
        : "r"(a[0]), "r"(a[1]), "r"(a[2]), "r"(a[3]), "r"(b0), "r"(b1));
}
__device__ __forceinline__ int swz64(int x) { return x ^ ((x >> 3) & 0x30); }

// ---------------------------------------------------------------------------
// K1: fused depthwise 3x3 at dilations 1/3/5, one (b,c) plane per block.
// ---------------------------------------------------------------------------
__global__ void k_depthwise(const float* __restrict__ x,
                            const float* __restrict__ w1, const float* __restrict__ b1,
                            const float* __restrict__ w2, const float* __restrict__ b2,
                            const float* __restrict__ w3, const float* __restrict__ b3) {
    __shared__ float xs[Nn];
    int bc = blockIdx.x;
    int c = bc & (Cc - 1);
    const float* xp = x + (size_t)bc * Nn;
    for (int i = threadIdx.x; i < Nn; i += blockDim.x) xs[i] = xp[i];

    float wa[9], wb[9], wc[9];
#pragma unroll
    for (int i = 0; i < 9; i++) {
        wa[i] = __ldg(&w1[c * 9 + i]);
        wb[i] = __ldg(&w2[c * 9 + i]);
        wc[i] = __ldg(&w3[c * 9 + i]);
    }
    float biasa = __ldg(&b1[c]), biasb = __ldg(&b2[c]), biasc = __ldg(&b3[c]);
    __syncthreads();

    for (int p = threadIdx.x; p < Nn; p += blockDim.x) {
        int h = p >> 6, w = p & 63;
        float d1 = biasa, d2 = biasb, d3 = biasc;
#pragma unroll
        for (int kh = 0; kh < 3; kh++) {
#pragma unroll
            for (int kw = 0; kw < 3; kw++) {
                int i = kh * 3 + kw;
                {
                    int hh = h + (kh - 1), ww = w + (kw - 1);
                    float v = ((unsigned)hh < 64u && (unsigned)ww < 64u) ? xs[(hh << 6) + ww] : 0.f;
                    d1 = fmaf(wa[i], v, d1);
                }
                {
                    int hh = h + (kh - 1) * 3, ww = w + (kw - 1) * 3;
                    float v = ((unsigned)hh < 64u && (unsigned)ww < 64u) ? xs[(hh << 6) + ww] : 0.f;
                    d2 = fmaf(wb[i], v, d2);
                }
                {
                    int hh = h + (kh - 1) * 5, ww = w + (kw - 1) * 5;
                    float v = ((unsigned)hh < 64u && (unsigned)ww < 64u) ? xs[(hh << 6) + ww] : 0.f;
                    d3 = fmaf(wc[i], v, d3);
                }
            }
        }
        g_D[0][(size_t)bc * Nn + p] = d1;
        g_D[1][(size_t)bc * Nn + p] = d2;
        g_D[2][(size_t)bc * Nn + p] = d3;
    }
}

// ---------------------------------------------------------------------------
// K2: pointwise 1x1 C->R per branch, f32x2 math, bf16 output [b][n][r].
// ---------------------------------------------------------------------------
__global__ void k_pointwise(const float* __restrict__ pw1, const float* __restrict__ pb1,
                            const float* __restrict__ pw2, const float* __restrict__ pb2,
                            const float* __restrict__ pw3, const float* __restrict__ pb3) {
    __shared__ ull wT2[Cc * 16];
    int k = blockIdx.z;
    const float* pw = (k == 0) ? pw1 : ((k == 1) ? pw2 : pw3);
    const float* pb = (k == 0) ? pb1 : ((k == 1) ? pb2 : pb3);

    for (int i = threadIdx.x; i < Cc * 16; i += blockDim.x) {
        int c = i >> 4, rp = i & 15;
        wT2[i] = pack2(pw[(2 * rp) * Cc + c], pw[(2 * rp + 1) * Cc + c]);
    }
    __syncthreads();

    int b = blockIdx.y;
    int n = blockIdx.x * blockDim.x + threadIdx.x;
    const float* Dk = g_D[k] + (size_t)b * Cc * Nn + n;

    ull acc2[16];
#pragma unroll
    for (int rp = 0; rp < 16; rp++) acc2[rp] = pack2(__ldg(&pb[2 * rp]), __ldg(&pb[2 * rp + 1]));

#pragma unroll 4
    for (int c = 0; c < Cc; c++) {
        float v = Dk[(size_t)c * Nn];
        ull v2 = pack2(v, v);
        const ulonglong2* w4 = (const ulonglong2*)(wT2 + c * 16);
#pragma unroll
        for (int t = 0; t < 8; t++) {
            ulonglong2 ww = w4[t];
            acc2[2 * t + 0] = fma2(v2, ww.x, acc2[2 * t + 0]);
            acc2[2 * t + 1] = fma2(v2, ww.y, acc2[2 * t + 1]);
        }
    }
    uint32 ob[16];
#pragma unroll
    for (int rp = 0; rp < 16; rp++) {
        float2 f = unpack2(acc2[rp]);
        ob[rp] = cvt2(f.y, f.x);    // lo = r even, hi = r odd
    }
    uint4* out = (uint4*)(g_Fpb[k] + ((size_t)b * Nn + n) * Rr);
#pragma unroll
    for (int q = 0; q < 4; q++)
        out[q] = make_uint4(ob[4 * q], ob[4 * q + 1], ob[4 * q + 2], ob[4 * q + 3]);
}

// ---------------------------------------------------------------------------
// K3: flash attention on tensor cores (mma.m16n8k16 bf16), split-KV.
// Q=Fpb[1], K=Fpb[2], V=Fpb[0]. Unshifted softmax; partials add.
// Block = 256 threads (8 warps), 128 queries; warp owns 16 query rows.
// ---------------------------------------------------------------------------
__global__ void __launch_bounds__(256) k_attn() {
    __shared__ __align__(16) unsigned char sm[16384];
    // Qs: [0,8192)  128 rows x 64B ; Ks: [8192,12288) 64x64B ; Vs: [12288,16384)
    const int t = threadIdx.x, lane = t & 31, w = t >> 5;
    const int b = blockIdx.y, split = blockIdx.z;
    const int i0 = blockIdx.x * 128;

    // stage Q (swizzled)
    const uint4* Qg = (const uint4*)(g_Fpb[1] + ((size_t)(b * Nn + i0)) * Rr);
#pragma unroll
    for (int id = t; id < 512; id += 256) {
        uint4 v = Qg[id];
        *(uint4*)(sm + swz64(id * 16)) = v;
    }
    __syncthreads();

    uint32 qbase = (uint32)__cvta_generic_to_shared(sm);
    uint32 kbase = qbase + 8192, vbase = qbase + 12288;

    // A fragments for Q (2 k-steps of 16)
    uint32 qa[2][4];
#pragma unroll
    for (int kc = 0; kc < 2; kc++) {
        int row = w * 16 + (lane & 15);
        int chunk = 2 * kc + (lane >> 4);
        ldsm4(qa[kc], qbase + swz64(row * 64 + chunk * 16));
    }

    float oacc[4][4];
#pragma unroll
    for (int a = 0; a < 4; a++)
#pragma unroll
        for (int c = 0; c < 4; c++) oacc[a][c] = 0.f;
    float lsum0 = 0.f, lsum1 = 0.f;

    const uint4* Kg = (const uint4*)(g_Fpb[2] + (size_t)b * Nn * Rr);
    const uint4* Vg = (const uint4*)(g_Fpb[0] + (size_t)b * Nn * Rr);
    const int j0 = split * KCHUNK;

    uint4 kreg = Kg[j0 * 4 + t];
    uint4 vreg = Vg[j0 * 4 + t];
    const int kv_dst = swz64(t * 16);

    for (int tl = 0; tl < NT; tl++) {
        *(uint4*)(sm + 8192 + kv_dst) = kreg;
        *(uint4*)(sm + 12288 + kv_dst) = vreg;
        __syncthreads();
        if (tl + 1 < NT) {
            kreg = Kg[(j0 + (tl + 1) * TK) * 4 + t];
            vreg = Vg[(j0 + (tl + 1) * TK) * 4 + t];
        }

        // ---- S = Q K^T : 8 n-blocks (64 keys) x 2 k-steps -------------------
        float sacc[8][4];
#pragma unroll
        for (int nb = 0; nb < 8; nb++)
#pragma unroll
            for (int c = 0; c < 4; c++) sacc[nb][c] = 0.f;

#pragma unroll
        for (int nb2 = 0; nb2 < 4; nb2++) {
#pragma unroll
            for (int ks = 0; ks < 2; ks++) {
                int row = nb2 * 16 + (lane & 7) + ((lane & 16) ? 8 : 0);
                int chunk = 2 * ks + ((lane >> 3) & 1);
                uint32 kb[4];
                ldsm4(kb, kbase + swz64(row * 64 + chunk * 16));
                mma16816(sacc[2 * nb2], qa[ks], kb[0], kb[1]);
                mma16816(sacc[2 * nb2 + 1], qa[ks], kb[2], kb[3]);
            }
        }

        // ---- P = exp(S); row-sum; pack to A fragments ------------------------
        uint32 pa[4][4];
#pragma unroll
        for (int nb = 0; nb < 8; nb++) {
            float e0 = __expf(sacc[nb][0]), e1 = __expf(sacc[nb][1]);
            float e2 = __expf(sacc[nb][2]), e3 = __expf(sacc[nb][3]);
            lsum0 += e0 + e1;
            lsum1 += e2 + e3;
            pa[nb >> 1][2 * (nb & 1) + 0] = cvt2(e1, e0);
            pa[nb >> 1][2 * (nb & 1) + 1] = cvt2(e3, e2);
        }

        // ---- O += P V : 4 k-steps (16 keys) x 4 d-blocks ---------------------
#pragma unroll
        for (int ks = 0; ks < 4; ks++) {
#pragma unroll
            for (int h = 0; h < 2; h++) {
                int row = ks * 16 + (lane & 15);
                int col = h * 16 + ((lane >> 4) * 8);
                uint32 vb[4];
                ldsm4t(vb, vbase + swz64(row * 64 + col * 2));
                mma16816(oacc[2 * h], pa[ks], vb[0], vb[1]);
                mma16816(oacc[2 * h + 1], pa[ks], vb[2], vb[3]);
            }
        }
        __syncthreads();
    }

    // reduce row sums across the quad (lanes sharing the same row)
    lsum0 += __shfl_xor_sync(0xffffffffu, lsum0, 1);
    lsum0 += __shfl_xor_sync(0xffffffffu, lsum0, 2);
    lsum1 += __shfl_xor_sync(0xffffffffu, lsum1, 1);
    lsum1 += __shfl_xor_sync(0xffffffffu, lsum1, 2);

    // store partial numerators + denominators
    int r = lane >> 2, c2 = 2 * (lane & 3);
    size_t rowbase = ((size_t)b * Nn + i0 + w * 16 + r) * Rr;
    float* Po = g_Po[split];
#pragma unroll
    for (int nb = 0; nb < 4; nb++) {
        *(float2*)(Po + rowbase + nb * 8 + c2) = make_float2(oacc[nb][0], oacc[nb][1]);
        *(float2*)(Po + rowbase + 8 * Rr + nb * 8 + c2) = make_float2(oacc[nb][2], oacc[nb][3]);
    }
    if ((lane & 3) == 0) {
        g_Pl[split][(size_t)b * Nn + i0 + w * 16 + r] = lsum0;
        g_Pl[split][(size_t)b * Nn + i0 + w * 16 + r + 8] = lsum1;
    }
}

// ---------------------------------------------------------------------------
// K3b: combine split partials -> g_O (normalized).
// ---------------------------------------------------------------------------
__global__ void k_comb() {
    int gid = blockIdx.x * blockDim.x + threadIdx.x;   // 0 .. B*N*8-1
    int chunk = gid & 7;
    int bn = gid >> 3;

    float l = 0.f;
#pragma unroll
    for (int s = 0; s < SPLIT; s++) l += g_Pl[s][bn];
    float inv = 1.0f / l;

    float4 acc = make_float4(0.f, 0.f, 0.f, 0.f);
#pragma unroll
    for (int s = 0; s < SPLIT; s++) {
        float4 v = ((const float4*)g_Po[s])[(size_t)bn * 8 + chunk];
        acc.x += v.x; acc.y += v.y; acc.z += v.z; acc.w += v.w;
    }
    ((float4*)g_O)[(size_t)bn * 8 + chunk] =
        make_float4(acc.x * inv, acc.y * inv, acc.z * inv, acc.w * inv);
}

// ---------------------------------------------------------------------------
// K4: conv_out 1x1 (R->C) + bias + residual. co split across blockIdx.z.
// ---------------------------------------------------------------------------
__global__ void k_out(const float* __restrict__ x, const float* __restrict__ cow,
                      const float* __restrict__ cob, float* __restrict__ out) {
    __shared__ ull ws2[32 * 16];
    int co0 = blockIdx.z * 32;
    for (int i = threadIdx.x; i < 32 * 16; i += blockDim.x) {
        int idx = 2 * i;
        ws2[i] = pack2(cow[co0 * Rr + idx], cow[co0 * Rr + idx + 1]);
    }
    __syncthreads();

    int b = blockIdx.y;
    int n = blockIdx.x * blockDim.x + threadIdx.x;

    const ulonglong2* O4 = (const ulonglong2*)(g_O + ((size_t)b * Nn + n) * Rr);
    ull o2[16];
#pragma unroll
    for (int t = 0; t < 8; t++) {
        ulonglong2 v = O4[t];
        o2[2 * t] = v.x; o2[2 * t + 1] = v.y;
    }

    size_t base = (size_t)b * Cc * Nn + n;
#pragma unroll 2
    for (int co = 0; co < 32; co++) {
        const ulonglong2* w4 = (const ulonglong2*)(ws2 + co * 16);
        ull sp0 = 0ULL, sp1 = 0ULL;
#pragma unroll
        for (int t = 0; t < 4; t++) {
            ulonglong2 ww0 = w4[2 * t];
            ulonglong2 ww1 = w4[2 * t + 1];
            sp0 = fma2(ww0.x, o2[4 * t + 0], sp0);
            sp1 = fma2(ww0.y, o2[4 * t + 1], sp1);
            sp0 = fma2(ww1.x, o2[4 * t + 2], sp0);
            sp1 = fma2(ww1.y, o2[4 * t + 3], sp1);
        }
        float2 sa = unpack2(sp0), sb = unpack2(sp1);
        size_t off = base + (size_t)(co0 + co) * Nn;
        out[off] = x[off] + ((sa.x + sa.y) + (sb.x + sb.y)) + __ldg(&cob[co0 + co]);
    }
}

// ---------------------------------------------------------------------------
extern "C" void kernel_launch(void* const* d_in, const int* in_sizes, int n_in,
                              void* d_out, int out_size) {
    const float* x = (const float*)d_in[0];
    k_depthwise<<<Bz * Cc, 256>>>(x,
        (const float*)d_in[1], (const float*)d_in[2],
        (const float*)d_in[5], (const float*)d_in[6],
        (const float*)d_in[9], (const float*)d_in[10]);

    dim3 g2(Nn / 128, Bz, 3);
    k_pointwise<<<g2, 128>>>(
        (const float*)d_in[3],  (const float*)d_in[4],
        (const float*)d_in[7],  (const float*)d_in[8],
        (const float*)d_in[11], (const float*)d_in[12]);

    k_attn<<<dim3(Nn / 128, Bz, SPLIT), 256>>>();

    k_comb<<<(Bz * Nn * 8) / 256, 256>>>();

    k_out<<<dim3(Nn / 128, Bz, Cc / 32), 128>>>(x, (const float*)d_in[13],
                                                (const float*)d_in[14], (float*)d_out);
}

// round 4
// speedup vs baseline: 4.6903x; 1.0106x over previous
#include <cuda_runtime.h>
#include <cuda_bf16.h>

#define Bz 4
#define Cc 256
#define Nn 4096
#define Rr 32
#define TK 64
#define SPLIT 4
#define KCHUNK (Nn / SPLIT)   // 1024 keys per split
#define NT (KCHUNK / TK)      // 16 key tiles per split

typedef unsigned long long ull;
typedef unsigned int uint32;
typedef unsigned short uint16;

// Scratch (static device arrays; no allocation anywhere)
__device__ __nv_bfloat16 g_Db[3][(size_t)Bz * Cc * Nn];            // depthwise outputs (bf16)
__device__ __align__(128) __nv_bfloat16 g_Fpb[3][(size_t)Bz * Nn * Rr];  // Q/K/V bf16 [b][n][r]
__device__ float g_Po[SPLIT][(size_t)Bz * Nn * Rr];                // attention partial numerators
__device__ float g_Pl[SPLIT][(size_t)Bz * Nn];                     // attention partial denominators

// ---- packed f32x2 helpers ---------------------------------------------------
__device__ __forceinline__ ull fma2(ull a, ull b, ull c) {
    ull d;
    asm("fma.rn.f32x2 %0, %1, %2, %3;" : "=l"(d) : "l"(a), "l"(b), "l"(c));
    return d;
}
__device__ __forceinline__ ull pack2(float x, float y) {
    ull r; asm("mov.b64 %0, {%1, %2};" : "=l"(r) : "f"(x), "f"(y)); return r;
}
__device__ __forceinline__ float2 unpack2(ull v) {
    float2 f; asm("mov.b64 {%0, %1}, %2;" : "=f"(f.x), "=f"(f.y) : "l"(v)); return f;
}
__device__ __forceinline__ uint32 cvt2(float hi, float lo) {
    uint32 d; asm("cvt.rn.bf16x2.f32 %0, %1, %2;" : "=r"(d) : "f"(hi), "f"(lo)); return d;
}
__device__ __forceinline__ float bf2f(uint16 h) {
    return __uint_as_float(((uint32)h) << 16);
}

// ---- tensor-core helpers ----------------------------------------------------
__device__ __forceinline__ void ldsm4(uint32 r[4], uint32 addr) {
    asm volatile("ldmatrix.sync.aligned.m8n8.x4.shared.b16 {%0,%1,%2,%3}, [%4];"
        : "=r"(r[0]), "=r"(r[1]), "=r"(r[2]), "=r"(r[3]) : "r"(addr));
}
__device__ __forceinline__ void ldsm4t(uint32 r[4], uint32 addr) {
    asm volatile("ldmatrix.sync.aligned.m8n8.x4.trans.shared.b16 {%0,%1,%2,%3}, [%4];"
        : "=r"(r[0]), "=r"(r[1]), "=r"(r[2]), "=r"(r[3]) : "r"(addr));
}
__device__ __forceinline__ void mma16816(float c[4], const uint32 a[4], uint32 b0, uint32 b1) {
    asm volatile("mma.sync.aligned.m16n8k16.row.col.f32.bf16.bf16.f32 "
        "{%0,%1,%2,%3}, {%4,%5,%6,%7}, {%8,%9}, {%0,%1,%2,%3};"
        : "+f"(c[0]), "+f"(c[1]), "+f"(c[2]), "+f"(c[3])
        : "r"(a[0]), "r"(a[1]), "r"(a[2]), "r"(a[3]), "r"(b0), "r"(b1));
}
__device__ __forceinline__ int swz64(int x) { return x ^ ((x >> 3) & 0x30); }

// ---------------------------------------------------------------------------
// K1: fused depthwise 3x3 at dilations 1/3/5, one (b,c) plane per block.
// Column-bound predicates hoisted (w is fixed per thread); bf16 output.
// ---------------------------------------------------------------------------
__global__ void __launch_bounds__(256) k_depthwise(const float* __restrict__ x,
                            const float* __restrict__ w1, const float* __restrict__ b1,
                            const float* __restrict__ w2, const float* __restrict__ b2,
                            const float* __restrict__ w3, const float* __restrict__ b3) {
    __shared__ float xs[Nn];
    int bc = blockIdx.x;
    int c = bc & (Cc - 1);
    const float* xp = x + (size_t)bc * Nn;
    for (int i = threadIdx.x; i < Nn; i += blockDim.x) xs[i] = xp[i];

    float wa[9], wb[9], wc[9];
#pragma unroll
    for (int i = 0; i < 9; i++) {
        wa[i] = __ldg(&w1[c * 9 + i]);
        wb[i] = __ldg(&w2[c * 9 + i]);
        wc[i] = __ldg(&w3[c * 9 + i]);
    }
    float biasa = __ldg(&b1[c]), biasb = __ldg(&b2[c]), biasc = __ldg(&b3[c]);

    const int w = threadIdx.x & 63;
    const int h0 = threadIdx.x >> 6;          // rows h0, h0+4, ..., h0+60
    // hoisted column validity per dilation (1,3,5) and kw (0,2); kw=1 always ok
    bool cokL[3], cokR[3];
    cokL[0] = (w >= 1);  cokR[0] = (w <= 62);
    cokL[1] = (w >= 3);  cokR[1] = (w <= 60);
    cokL[2] = (w >= 5);  cokR[2] = (w <= 58);
    const int dils[3] = {1, 3, 5};

    __syncthreads();

#pragma unroll 4
    for (int i = 0; i < 16; i++) {
        int h = h0 + 4 * i;
        int p = (h << 6) + w;
        float d[3] = {biasa, biasb, biasc};
        const float* wk[3] = {wa, wb, wc};
#pragma unroll
        for (int dd = 0; dd < 3; dd++) {
            int dil = dils[dd];
#pragma unroll
            for (int kh = 0; kh < 3; kh++) {
                int hh = h + (kh - 1) * dil;
                if ((unsigned)hh < 64u) {
                    const float* row = xs + (hh << 6) + w;
                    float acc = d[dd];
                    if (cokL[dd]) acc = fmaf(wk[dd][kh * 3 + 0], row[-dil], acc);
                    acc = fmaf(wk[dd][kh * 3 + 1], row[0], acc);
                    if (cokR[dd]) acc = fmaf(wk[dd][kh * 3 + 2], row[dil], acc);
                    d[dd] = acc;
                }
            }
        }
        size_t off = (size_t)bc * Nn + p;
        g_Db[0][off] = __float2bfloat16(d[0]);
        g_Db[1][off] = __float2bfloat16(d[1]);
        g_Db[2][off] = __float2bfloat16(d[2]);
    }
}

// ---------------------------------------------------------------------------
// K2: pointwise 1x1 C->R per branch, bf16 in (shift-convert), f32x2 math,
// bf16 output [b][n][r].
// ---------------------------------------------------------------------------
__global__ void k_pointwise(const float* __restrict__ pw1, const float* __restrict__ pb1,
                            const float* __restrict__ pw2, const float* __restrict__ pb2,
                            const float* __restrict__ pw3, const float* __restrict__ pb3) {
    __shared__ ull wT2[Cc * 16];
    int k = blockIdx.z;
    const float* pw = (k == 0) ? pw1 : ((k == 1) ? pw2 : pw3);
    const float* pb = (k == 0) ? pb1 : ((k == 1) ? pb2 : pb3);

    for (int i = threadIdx.x; i < Cc * 16; i += blockDim.x) {
        int c = i >> 4, rp = i & 15;
        wT2[i] = pack2(pw[(2 * rp) * Cc + c], pw[(2 * rp + 1) * Cc + c]);
    }
    __syncthreads();

    int b = blockIdx.y;
    int n = blockIdx.x * blockDim.x + threadIdx.x;
    const uint16* Dk = (const uint16*)g_Db[k] + (size_t)b * Cc * Nn + n;

    ull acc2[16];
#pragma unroll
    for (int rp = 0; rp < 16; rp++) acc2[rp] = pack2(__ldg(&pb[2 * rp]), __ldg(&pb[2 * rp + 1]));

#pragma unroll 4
    for (int c = 0; c < Cc; c++) {
        float v = bf2f(__ldg(Dk + (size_t)c * Nn));
        ull v2 = pack2(v, v);
        const ulonglong2* w4 = (const ulonglong2*)(wT2 + c * 16);
#pragma unroll
        for (int t = 0; t < 8; t++) {
            ulonglong2 ww = w4[t];
            acc2[2 * t + 0] = fma2(v2, ww.x, acc2[2 * t + 0]);
            acc2[2 * t + 1] = fma2(v2, ww.y, acc2[2 * t + 1]);
        }
    }
    uint32 ob[16];
#pragma unroll
    for (int rp = 0; rp < 16; rp++) {
        float2 f = unpack2(acc2[rp]);
        ob[rp] = cvt2(f.y, f.x);
    }
    uint4* out = (uint4*)(g_Fpb[k] + ((size_t)b * Nn + n) * Rr);
#pragma unroll
    for (int q = 0; q < 4; q++)
        out[q] = make_uint4(ob[4 * q], ob[4 * q + 1], ob[4 * q + 2], ob[4 * q + 3]);
}

// ---------------------------------------------------------------------------
// K3: flash attention on tensor cores (mma.m16n8k16 bf16), split-KV.
// Q=Fpb[1], K=Fpb[2], V=Fpb[0]. Unshifted softmax; partials add.
// ---------------------------------------------------------------------------
__global__ void __launch_bounds__(256) k_attn() {
    __shared__ __align__(16) unsigned char sm[16384];
    const int t = threadIdx.x, lane = t & 31, w = t >> 5;
    const int b = blockIdx.y, split = blockIdx.z;
    const int i0 = blockIdx.x * 128;

    const uint4* Qg = (const uint4*)(g_Fpb[1] + ((size_t)(b * Nn + i0)) * Rr);
#pragma unroll
    for (int id = t; id < 512; id += 256) {
        uint4 v = Qg[id];
        *(uint4*)(sm + swz64(id * 16)) = v;
    }
    __syncthreads();

    uint32 qbase = (uint32)__cvta_generic_to_shared(sm);
    uint32 kbase = qbase + 8192, vbase = qbase + 12288;

    uint32 qa[2][4];
#pragma unroll
    for (int kc = 0; kc < 2; kc++) {
        int row = w * 16 + (lane & 15);
        int chunk = 2 * kc + (lane >> 4);
        ldsm4(qa[kc], qbase + swz64(row * 64 + chunk * 16));
    }

    float oacc[4][4];
#pragma unroll
    for (int a = 0; a < 4; a++)
#pragma unroll
        for (int c = 0; c < 4; c++) oacc[a][c] = 0.f;
    float lsum0 = 0.f, lsum1 = 0.f;

    const uint4* Kg = (const uint4*)(g_Fpb[2] + (size_t)b * Nn * Rr);
    const uint4* Vg = (const uint4*)(g_Fpb[0] + (size_t)b * Nn * Rr);
    const int j0 = split * KCHUNK;

    uint4 kreg = Kg[j0 * 4 + t];
    uint4 vreg = Vg[j0 * 4 + t];
    const int kv_dst = swz64(t * 16);

    for (int tl = 0; tl < NT; tl++) {
        *(uint4*)(sm + 8192 + kv_dst) = kreg;
        *(uint4*)(sm + 12288 + kv_dst) = vreg;
        __syncthreads();
        if (tl + 1 < NT) {
            kreg = Kg[(j0 + (tl + 1) * TK) * 4 + t];
            vreg = Vg[(j0 + (tl + 1) * TK) * 4 + t];
        }

        float sacc[8][4];
#pragma unroll
        for (int nb = 0; nb < 8; nb++)
#pragma unroll
            for (int c = 0; c < 4; c++) sacc[nb][c] = 0.f;

#pragma unroll
        for (int nb2 = 0; nb2 < 4; nb2++) {
#pragma unroll
            for (int ks = 0; ks < 2; ks++) {
                int row = nb2 * 16 + (lane & 7) + ((lane & 16) ? 8 : 0);
                int chunk = 2 * ks + ((lane >> 3) & 1);
                uint32 kb[4];
                ldsm4(kb, kbase + swz64(row * 64 + chunk * 16));
                mma16816(sacc[2 * nb2], qa[ks], kb[0], kb[1]);
                mma16816(sacc[2 * nb2 + 1], qa[ks], kb[2], kb[3]);
            }
        }

        uint32 pa[4][4];
#pragma unroll
        for (int nb = 0; nb < 8; nb++) {
            float e0 = __expf(sacc[nb][0]), e1 = __expf(sacc[nb][1]);
            float e2 = __expf(sacc[nb][2]), e3 = __expf(sacc[nb][3]);
            lsum0 += e0 + e1;
            lsum1 += e2 + e3;
            pa[nb >> 1][2 * (nb & 1) + 0] = cvt2(e1, e0);
            pa[nb >> 1][2 * (nb & 1) + 1] = cvt2(e3, e2);
        }

#pragma unroll
        for (int ks = 0; ks < 4; ks++) {
#pragma unroll
            for (int h = 0; h < 2; h++) {
                int row = ks * 16 + (lane & 15);
                int col = h * 16 + ((lane >> 4) * 8);
                uint32 vb[4];
                ldsm4t(vb, vbase + swz64(row * 64 + col * 2));
                mma16816(oacc[2 * h], pa[ks], vb[0], vb[1]);
                mma16816(oacc[2 * h + 1], pa[ks], vb[2], vb[3]);
            }
        }
        __syncthreads();
    }

    lsum0 += __shfl_xor_sync(0xffffffffu, lsum0, 1);
    lsum0 += __shfl_xor_sync(0xffffffffu, lsum0, 2);
    lsum1 += __shfl_xor_sync(0xffffffffu, lsum1, 1);
    lsum1 += __shfl_xor_sync(0xffffffffu, lsum1, 2);

    int r = lane >> 2, c2 = 2 * (lane & 3);
    size_t rowbase = ((size_t)b * Nn + i0 + w * 16 + r) * Rr;
    float* Po = g_Po[split];
#pragma unroll
    for (int nb = 0; nb < 4; nb++) {
        *(float2*)(Po + rowbase + nb * 8 + c2) = make_float2(oacc[nb][0], oacc[nb][1]);
        *(float2*)(Po + rowbase + 8 * Rr + nb * 8 + c2) = make_float2(oacc[nb][2], oacc[nb][3]);
    }
    if ((lane & 3) == 0) {
        g_Pl[split][(size_t)b * Nn + i0 + w * 16 + r] = lsum0;
        g_Pl[split][(size_t)b * Nn + i0 + w * 16 + r + 8] = lsum1;
    }
}

// ---------------------------------------------------------------------------
// K4: combine split partials + conv_out 1x1 (R->C) + bias + residual.
// co-split=2 across blockIdx.z; one position per thread.
// ---------------------------------------------------------------------------
__global__ void __launch_bounds__(128) k_out(const float* __restrict__ x,
                      const float* __restrict__ cow,
                      const float* __restrict__ cob, float* __restrict__ out) {
    __shared__ ull ws2[128 * 16];   // 128 co x 32 r as pairs, 16 KB
    int co0 = blockIdx.z * 128;
    for (int i = threadIdx.x; i < 128 * 16; i += blockDim.x) {
        int idx = 2 * i;
        ws2[i] = pack2(cow[co0 * Rr + idx], cow[co0 * Rr + idx + 1]);
    }
    __syncthreads();

    int b = blockIdx.y;
    int n = blockIdx.x * blockDim.x + threadIdx.x;
    size_t bn = (size_t)b * Nn + n;

    // combine split-KV partials inline
    float l = 0.f;
#pragma unroll
    for (int s = 0; s < SPLIT; s++) l += g_Pl[s][bn];
    float inv = 1.0f / l;
    ull inv2 = pack2(inv, inv);

    ull o2[16];
#pragma unroll
    for (int t = 0; t < 16; t++) o2[t] = 0ULL;
#pragma unroll
    for (int s = 0; s < SPLIT; s++) {
        const ulonglong2* Po = (const ulonglong2*)(g_Po[s] + bn * Rr);
#pragma unroll
        for (int t = 0; t < 8; t++) {
            ulonglong2 v = Po[t];
            float2 a = unpack2(o2[2 * t]), bb = unpack2(v.x);
            o2[2 * t] = pack2(a.x + bb.x, a.y + bb.y);
            float2 c = unpack2(o2[2 * t + 1]), d = unpack2(v.y);
            o2[2 * t + 1] = pack2(c.x + d.x, c.y + d.y);
        }
    }
#pragma unroll
    for (int t = 0; t < 16; t++) {
        float2 a = unpack2(o2[t]);
        o2[t] = pack2(a.x * inv, a.y * inv);
    }

    size_t base = (size_t)b * Cc * Nn + n;
#pragma unroll 2
    for (int co = 0; co < 128; co++) {
        const ulonglong2* w4 = (const ulonglong2*)(ws2 + co * 16);
        ull sp0 = 0ULL, sp1 = 0ULL;
#pragma unroll
        for (int t = 0; t < 4; t++) {
            ulonglong2 ww0 = w4[2 * t];
            ulonglong2 ww1 = w4[2 * t + 1];
            sp0 = fma2(ww0.x, o2[4 * t + 0], sp0);
            sp1 = fma2(ww0.y, o2[4 * t + 1], sp1);
            sp0 = fma2(ww1.x, o2[4 * t + 2], sp0);
            sp1 = fma2(ww1.y, o2[4 * t + 3], sp1);
        }
        float2 sa = unpack2(sp0), sb = unpack2(sp1);
        size_t off = base + (size_t)(co0 + co) * Nn;
        out[off] = x[off] + ((sa.x + sa.y) + (sb.x + sb.y)) + __ldg(&cob[co0 + co]);
    }
}

// ---------------------------------------------------------------------------
extern "C" void kernel_launch(void* const* d_in, const int* in_sizes, int n_in,
                              void* d_out, int out_size) {
    const float* x = (const float*)d_in[0];
    k_depthwise<<<Bz * Cc, 256>>>(x,
        (const float*)d_in[1], (const float*)d_in[2],
        (const float*)d_in[5], (const float*)d_in[6],
        (const float*)d_in[9], (const float*)d_in[10]);

    dim3 g2(Nn / 128, Bz, 3);
    k_pointwise<<<g2, 128>>>(
        (const float*)d_in[3],  (const float*)d_in[4],
        (const float*)d_in[7],  (const float*)d_in[8],
        (const float*)d_in[11], (const float*)d_in[12]);

    k_attn<<<dim3(Nn / 128, Bz, SPLIT), 256>>>();

    k_out<<<dim3(Nn / 128, Bz, 2), 128>>>(x, (const float*)d_in[13],
                                          (const float*)d_in[14], (float*)d_out);
}

// round 5
// speedup vs baseline: 4.9490x; 1.0552x over previous
#include <cuda_runtime.h>
#include <cuda_bf16.h>

#define Bz 4
#define Cc 256
#define Nn 4096
#define Rr 32
#define TK 64
#define SPLIT 4
#define KCHUNK (Nn / SPLIT)   // 1024 keys per split
#define NT (KCHUNK / TK)      // 16 key tiles per split
#define LOG2E 1.4426950408889634f

typedef unsigned long long ull;
typedef unsigned int uint32;
typedef unsigned short uint16;

// Scratch (static device arrays; no allocation anywhere)
__device__ __nv_bfloat16 g_Db[3][(size_t)Bz * Cc * Nn];            // depthwise outputs (bf16)
__device__ __align__(128) __nv_bfloat16 g_Fpb[3][(size_t)Bz * Nn * Rr];  // Q/K/V bf16 [b][n][r]
__device__ float g_Po[SPLIT][(size_t)Bz * Nn * Rr];                // attention partial numerators
__device__ float g_Pl[SPLIT][(size_t)Bz * Nn];                     // attention partial denominators

// ---- packed f32x2 helpers ---------------------------------------------------
__device__ __forceinline__ ull fma2(ull a, ull b, ull c) {
    ull d;
    asm("fma.rn.f32x2 %0, %1, %2, %3;" : "=l"(d) : "l"(a), "l"(b), "l"(c));
    return d;
}
__device__ __forceinline__ ull pack2(float x, float y) {
    ull r; asm("mov.b64 %0, {%1, %2};" : "=l"(r) : "f"(x), "f"(y)); return r;
}
__device__ __forceinline__ float2 unpack2(ull v) {
    float2 f; asm("mov.b64 {%0, %1}, %2;" : "=f"(f.x), "=f"(f.y) : "l"(v)); return f;
}
__device__ __forceinline__ uint32 cvt2(float hi, float lo) {
    uint32 d; asm("cvt.rn.bf16x2.f32 %0, %1, %2;" : "=r"(d) : "f"(hi), "f"(lo)); return d;
}
__device__ __forceinline__ float bf2f(uint16 h) {
    return __uint_as_float(((uint32)h) << 16);
}
__device__ __forceinline__ float ex2f(float x) {
    float d; asm("ex2.approx.ftz.f32 %0, %1;" : "=f"(d) : "f"(x)); return d;
}

// ---- tensor-core helpers ----------------------------------------------------
__device__ __forceinline__ void ldsm4(uint32 r[4], uint32 addr) {
    asm volatile("ldmatrix.sync.aligned.m8n8.x4.shared.b16 {%0,%1,%2,%3}, [%4];"
        : "=r"(r[0]), "=r"(r[1]), "=r"(r[2]), "=r"(r[3]) : "r"(addr));
}
__device__ __forceinline__ void ldsm4t(uint32 r[4], uint32 addr) {
    asm volatile("ldmatrix.sync.aligned.m8n8.x4.trans.shared.b16 {%0,%1,%2,%3}, [%4];"
        : "=r"(r[0]), "=r"(r[1]), "=r"(r[2]), "=r"(r[3]) : "r"(addr));
}
__device__ __forceinline__ void mma16816(float c[4], const uint32 a[4], uint32 b0, uint32 b1) {
    asm volatile("mma.sync.aligned.m16n8k16.row.col.f32.bf16.bf16.f32 "
        "{%0,%1,%2,%3}, {%4,%5,%6,%7}, {%8,%9}, {%0,%1,%2,%3};"
        : "+f"(c[0]), "+f"(c[1]), "+f"(c[2]), "+f"(c[3])
        : "r"(a[0]), "r"(a[1]), "r"(a[2]), "r"(a[3]), "r"(b0), "r"(b1));
}
__device__ __forceinline__ int swz64(int x) { return x ^ ((x >> 3) & 0x30); }

// ---------------------------------------------------------------------------
// K1: fused depthwise 3x3 at dilations 1/3/5, one (b,c) plane per block.
// ---------------------------------------------------------------------------
__global__ void __launch_bounds__(256) k_depthwise(const float* __restrict__ x,
                            const float* __restrict__ w1, const float* __restrict__ b1,
                            const float* __restrict__ w2, const float* __restrict__ b2,
                            const float* __restrict__ w3, const float* __restrict__ b3) {
    __shared__ float xs[Nn];
    int bc = blockIdx.x;
    int c = bc & (Cc - 1);
    const float* xp = x + (size_t)bc * Nn;
    for (int i = threadIdx.x; i < Nn; i += blockDim.x) xs[i] = xp[i];

    float wa[9], wb[9], wc[9];
#pragma unroll
    for (int i = 0; i < 9; i++) {
        wa[i] = __ldg(&w1[c * 9 + i]);
        wb[i] = __ldg(&w2[c * 9 + i]);
        wc[i] = __ldg(&w3[c * 9 + i]);
    }
    float biasa = __ldg(&b1[c]), biasb = __ldg(&b2[c]), biasc = __ldg(&b3[c]);

    const int w = threadIdx.x & 63;
    const int h0 = threadIdx.x >> 6;
    bool cokL[3], cokR[3];
    cokL[0] = (w >= 1);  cokR[0] = (w <= 62);
    cokL[1] = (w >= 3);  cokR[1] = (w <= 60);
    cokL[2] = (w >= 5);  cokR[2] = (w <= 58);
    const int dils[3] = {1, 3, 5};

    __syncthreads();

#pragma unroll 4
    for (int i = 0; i < 16; i++) {
        int h = h0 + 4 * i;
        int p = (h << 6) + w;
        float d[3] = {biasa, biasb, biasc};
        const float* wk[3] = {wa, wb, wc};
#pragma unroll
        for (int dd = 0; dd < 3; dd++) {
            int dil = dils[dd];
#pragma unroll
            for (int kh = 0; kh < 3; kh++) {
                int hh = h + (kh - 1) * dil;
                if ((unsigned)hh < 64u) {
                    const float* row = xs + (hh << 6) + w;
                    float acc = d[dd];
                    if (cokL[dd]) acc = fmaf(wk[dd][kh * 3 + 0], row[-dil], acc);
                    acc = fmaf(wk[dd][kh * 3 + 1], row[0], acc);
                    if (cokR[dd]) acc = fmaf(wk[dd][kh * 3 + 2], row[dil], acc);
                    d[dd] = acc;
                }
            }
        }
        size_t off = (size_t)bc * Nn + p;
        g_Db[0][off] = __float2bfloat16(d[0]);
        g_Db[1][off] = __float2bfloat16(d[1]);
        g_Db[2][off] = __float2bfloat16(d[2]);
    }
}

// ---------------------------------------------------------------------------
// K2: pointwise 1x1 C->R per branch, bf16 in, f32x2 math, bf16 out [b][n][r].
// Branch k==2 (attention K = Fp3) is pre-scaled by log2e so k_attn can use
// raw ex2 instead of mul+ex2.
// ---------------------------------------------------------------------------
__global__ void k_pointwise(const float* __restrict__ pw1, const float* __restrict__ pb1,
                            const float* __restrict__ pw2, const float* __restrict__ pb2,
                            const float* __restrict__ pw3, const float* __restrict__ pb3) {
    __shared__ ull wT2[Cc * 16];
    int k = blockIdx.z;
    const float* pw = (k == 0) ? pw1 : ((k == 1) ? pw2 : pw3);
    const float* pb = (k == 0) ? pb1 : ((k == 1) ? pb2 : pb3);

    for (int i = threadIdx.x; i < Cc * 16; i += blockDim.x) {
        int c = i >> 4, rp = i & 15;
        wT2[i] = pack2(pw[(2 * rp) * Cc + c], pw[(2 * rp + 1) * Cc + c]);
    }
    __syncthreads();

    int b = blockIdx.y;
    int n = blockIdx.x * blockDim.x + threadIdx.x;
    const uint16* Dk = (const uint16*)g_Db[k] + (size_t)b * Cc * Nn + n;

    ull acc2[16];
#pragma unroll
    for (int rp = 0; rp < 16; rp++) acc2[rp] = pack2(__ldg(&pb[2 * rp]), __ldg(&pb[2 * rp + 1]));

#pragma unroll 4
    for (int c = 0; c < Cc; c++) {
        float v = bf2f(__ldg(Dk + (size_t)c * Nn));
        ull v2 = pack2(v, v);
        const ulonglong2* w4 = (const ulonglong2*)(wT2 + c * 16);
#pragma unroll
        for (int t = 0; t < 8; t++) {
            ulonglong2 ww = w4[t];
            acc2[2 * t + 0] = fma2(v2, ww.x, acc2[2 * t + 0]);
            acc2[2 * t + 1] = fma2(v2, ww.y, acc2[2 * t + 1]);
        }
    }
    float scale = (k == 2) ? LOG2E : 1.0f;
    uint32 ob[16];
#pragma unroll
    for (int rp = 0; rp < 16; rp++) {
        float2 f = unpack2(acc2[rp]);
        ob[rp] = cvt2(f.y * scale, f.x * scale);
    }
    uint4* out = (uint4*)(g_Fpb[k] + ((size_t)b * Nn + n) * Rr);
#pragma unroll
    for (int q = 0; q < 4; q++)
        out[q] = make_uint4(ob[4 * q], ob[4 * q + 1], ob[4 * q + 2], ob[4 * q + 3]);
}

// ---------------------------------------------------------------------------
// K3: flash attention on tensor cores (mma.m16n8k16 bf16), split-KV.
// Q=Fpb[1], K=Fpb[2] (pre-scaled by log2e), V=Fpb[0]. Unshifted softmax.
// ---------------------------------------------------------------------------
__global__ void __launch_bounds__(256) k_attn() {
    __shared__ __align__(16) unsigned char sm[16384];
    const int t = threadIdx.x, lane = t & 31, w = t >> 5;
    const int b = blockIdx.y, split = blockIdx.z;
    const int i0 = blockIdx.x * 128;

    const uint4* Qg = (const uint4*)(g_Fpb[1] + ((size_t)(b * Nn + i0)) * Rr);
#pragma unroll
    for (int id = t; id < 512; id += 256) {
        uint4 v = Qg[id];
        *(uint4*)(sm + swz64(id * 16)) = v;
    }
    __syncthreads();

    uint32 qbase = (uint32)__cvta_generic_to_shared(sm);
    uint32 kbase = qbase + 8192, vbase = qbase + 12288;

    uint32 qa[2][4];
#pragma unroll
    for (int kc = 0; kc < 2; kc++) {
        int row = w * 16 + (lane & 15);
        int chunk = 2 * kc + (lane >> 4);
        ldsm4(qa[kc], qbase + swz64(row * 64 + chunk * 16));
    }

    float oacc[4][4];
#pragma unroll
    for (int a = 0; a < 4; a++)
#pragma unroll
        for (int c = 0; c < 4; c++) oacc[a][c] = 0.f;
    float lsum0 = 0.f, lsum1 = 0.f;

    const uint4* Kg = (const uint4*)(g_Fpb[2] + (size_t)b * Nn * Rr);
    const uint4* Vg = (const uint4*)(g_Fpb[0] + (size_t)b * Nn * Rr);
    const int j0 = split * KCHUNK;

    uint4 kreg = Kg[j0 * 4 + t];
    uint4 vreg = Vg[j0 * 4 + t];
    const int kv_dst = swz64(t * 16);

    for (int tl = 0; tl < NT; tl++) {
        *(uint4*)(sm + 8192 + kv_dst) = kreg;
        *(uint4*)(sm + 12288 + kv_dst) = vreg;
        __syncthreads();
        if (tl + 1 < NT) {
            kreg = Kg[(j0 + (tl + 1) * TK) * 4 + t];
            vreg = Vg[(j0 + (tl + 1) * TK) * 4 + t];
        }

        float sacc[8][4];
#pragma unroll
        for (int nb = 0; nb < 8; nb++)
#pragma unroll
            for (int c = 0; c < 4; c++) sacc[nb][c] = 0.f;

#pragma unroll
        for (int nb2 = 0; nb2 < 4; nb2++) {
#pragma unroll
            for (int ks = 0; ks < 2; ks++) {
                int row = nb2 * 16 + (lane & 7) + ((lane & 16) ? 8 : 0);
                int chunk = 2 * ks + ((lane >> 3) & 1);
                uint32 kb[4];
                ldsm4(kb, kbase + swz64(row * 64 + chunk * 16));
                mma16816(sacc[2 * nb2], qa[ks], kb[0], kb[1]);
                mma16816(sacc[2 * nb2 + 1], qa[ks], kb[2], kb[3]);
            }
        }

        uint32 pa[4][4];
#pragma unroll
        for (int nb = 0; nb < 8; nb++) {
            float e0 = ex2f(sacc[nb][0]), e1 = ex2f(sacc[nb][1]);
            float e2 = ex2f(sacc[nb][2]), e3 = ex2f(sacc[nb][3]);
            lsum0 += e0 + e1;
            lsum1 += e2 + e3;
            pa[nb >> 1][2 * (nb & 1) + 0] = cvt2(e1, e0);
            pa[nb >> 1][2 * (nb & 1) + 1] = cvt2(e3, e2);
        }

#pragma unroll
        for (int ks = 0; ks < 4; ks++) {
#pragma unroll
            for (int h = 0; h < 2; h++) {
                int row = ks * 16 + (lane & 15);
                int col = h * 16 + ((lane >> 4) * 8);
                uint32 vb[4];
                ldsm4t(vb, vbase + swz64(row * 64 + col * 2));
                mma16816(oacc[2 * h], pa[ks], vb[0], vb[1]);
                mma16816(oacc[2 * h + 1], pa[ks], vb[2], vb[3]);
            }
        }
        __syncthreads();
    }

    lsum0 += __shfl_xor_sync(0xffffffffu, lsum0, 1);
    lsum0 += __shfl_xor_sync(0xffffffffu, lsum0, 2);
    lsum1 += __shfl_xor_sync(0xffffffffu, lsum1, 1);
    lsum1 += __shfl_xor_sync(0xffffffffu, lsum1, 2);

    int r = lane >> 2, c2 = 2 * (lane & 3);
    size_t rowbase = ((size_t)b * Nn + i0 + w * 16 + r) * Rr;
    float* Po = g_Po[split];
#pragma unroll
    for (int nb = 0; nb < 4; nb++) {
        *(float2*)(Po + rowbase + nb * 8 + c2) = make_float2(oacc[nb][0], oacc[nb][1]);
        *(float2*)(Po + rowbase + 8 * Rr + nb * 8 + c2) = make_float2(oacc[nb][2], oacc[nb][3]);
    }
    if ((lane & 3) == 0) {
        g_Pl[split][(size_t)b * Nn + i0 + w * 16 + r] = lsum0;
        g_Pl[split][(size_t)b * Nn + i0 + w * 16 + r + 8] = lsum1;
    }
}

// ---------------------------------------------------------------------------
// K4: combine split partials + conv_out 1x1 (R->C) + bias + residual.
// co-split=8 (32 co per block) -> grid 1024 blocks for occupancy; split
// partials re-combined per block (L2-resident, cheap).
// ---------------------------------------------------------------------------
__global__ void __launch_bounds__(128) k_out(const float* __restrict__ x,
                      const float* __restrict__ cow,
                      const float* __restrict__ cob, float* __restrict__ out) {
    __shared__ ull ws2[32 * 16];    // 32 co x 32 r as pairs, 4 KB
    int co0 = blockIdx.z * 32;
    for (int i = threadIdx.x; i < 32 * 16; i += blockDim.x) {
        int idx = 2 * i;
        ws2[i] = pack2(cow[co0 * Rr + idx], cow[co0 * Rr + idx + 1]);
    }
    __syncthreads();

    int b = blockIdx.y;
    int n = blockIdx.x * blockDim.x + threadIdx.x;
    size_t bn = (size_t)b * Nn + n;

    float l = 0.f;
#pragma unroll
    for (int s = 0; s < SPLIT; s++) l += g_Pl[s][bn];
    float inv = 1.0f / l;

    ull o2[16];
#pragma unroll
    for (int t = 0; t < 16; t++) o2[t] = 0ULL;
#pragma unroll
    for (int s = 0; s < SPLIT; s++) {
        const ulonglong2* Po = (const ulonglong2*)(g_Po[s] + bn * Rr);
#pragma unroll
        for (int t = 0; t < 8; t++) {
            ulonglong2 v = Po[t];
            float2 a = unpack2(o2[2 * t]), bb = unpack2(v.x);
            o2[2 * t] = pack2(a.x + bb.x, a.y + bb.y);
            float2 c = unpack2(o2[2 * t + 1]), d = unpack2(v.y);
            o2[2 * t + 1] = pack2(c.x + d.x, c.y + d.y);
        }
    }
#pragma unroll
    for (int t = 0; t < 16; t++) {
        float2 a = unpack2(o2[t]);
        o2[t] = pack2(a.x * inv, a.y * inv);
    }

    size_t base = (size_t)b * Cc * Nn + n;
#pragma unroll 2
    for (int co = 0; co < 32; co++) {
        const ulonglong2* w4 = (const ulonglong2*)(ws2 + co * 16);
        ull sp0 = 0ULL, sp1 = 0ULL;
#pragma unroll
        for (int t = 0; t < 4; t++) {
            ulonglong2 ww0 = w4[2 * t];
            ulonglong2 ww1 = w4[2 * t + 1];
            sp0 = fma2(ww0.x, o2[4 * t + 0], sp0);
            sp1 = fma2(ww0.y, o2[4 * t + 1], sp1);
            sp0 = fma2(ww1.x, o2[4 * t + 2], sp0);
            sp1 = fma2(ww1.y, o2[4 * t + 3], sp1);
        }
        float2 sa = unpack2(sp0), sb = unpack2(sp1);
        size_t off = base + (size_t)(co0 + co) * Nn;
        out[off] = x[off] + ((sa.x + sa.y) + (sb.x + sb.y)) + __ldg(&cob[co0 + co]);
    }
}

// ---------------------------------------------------------------------------
extern "C" void kernel_launch(void* const* d_in, const int* in_sizes, int n_in,
                              void* d_out, int out_size) {
    const float* x = (const float*)d_in[0];
    k_depthwise<<<Bz * Cc, 256>>>(x,
        (const float*)d_in[1], (const float*)d_in[2],
        (const float*)d_in[5], (const float*)d_in[6],
        (const float*)d_in[9], (const float*)d_in[10]);

    dim3 g2(Nn / 128, Bz, 3);
    k_pointwise<<<g2, 128>>>(
        (const float*)d_in[3],  (const float*)d_in[4],
        (const float*)d_in[7],  (const float*)d_in[8],
        (const float*)d_in[11], (const float*)d_in[12]);

    k_attn<<<dim3(Nn / 128, Bz, SPLIT), 256>>>();

    k_out<<<dim3(Nn / 128, Bz, 8), 128>>>(x, (const float*)d_in[13],
                                          (const float*)d_in[14], (float*)d_out);
}